// round 2
// baseline (speedup 1.0000x reference)
#include <cuda_runtime.h>

#define N_LAYERS 32
#define N_SUB    8
#define TPB      256
#define PAIRS    4          // f32x2 pairs per thread = 8 elements/thread

typedef unsigned long long u64;

__device__ __forceinline__ u64 pack2(float a, float b) {
    u64 r;
    asm("mov.b64 %0, {%1, %2};" : "=l"(r) : "f"(a), "f"(b));
    return r;
}
__device__ __forceinline__ void unpack2(u64 v, float& a, float& b) {
    asm("mov.b64 {%0, %1}, %2;" : "=f"(a), "=f"(b) : "l"(v));
}
__device__ __forceinline__ u64 fma2(u64 a, u64 b, u64 c) {
    u64 d;
    asm("fma.rn.f32x2 %0, %1, %2, %3;" : "=l"(d) : "l"(a), "l"(b), "l"(c));
    return d;
}

// tanh of both f32 lanes via one MUFU f16x2 op.
__device__ __forceinline__ u64 tanh2(u64 x) {
    float lo, hi;
    asm("mov.b64 {%0, %1}, %2;" : "=f"(lo), "=f"(hi) : "l"(x));
    unsigned th;
    // cvt.rn.f16x2.f32 d, a, b : d.high = cvt(a), d.low = cvt(b)
    asm("cvt.rn.f16x2.f32 %0, %1, %2;" : "=r"(th) : "f"(hi), "f"(lo));
    asm("tanh.approx.f16x2 %0, %0;" : "+r"(th));
    unsigned short hlo, hhi;
    asm("mov.b32 {%0, %1}, %2;" : "=h"(hlo), "=h"(hhi) : "r"(th));
    float tlo, thi;
    asm("cvt.f32.f16 %0, %1;" : "=f"(tlo) : "h"(hlo));
    asm("cvt.f32.f16 %0, %1;" : "=f"(thi) : "h"(hhi));
    u64 r;
    asm("mov.b64 %0, {%1, %2};" : "=l"(r) : "f"(tlo), "f"(thi));
    return r;
}

#define SIGNMASK2 0x8000000080000000ULL

__global__ __launch_bounds__(TPB)
void sympnet_kernel(const float4* __restrict__ x,
                    const float*  __restrict__ act_w,
                    const float*  __restrict__ bias_b,
                    const float*  __restrict__ lin_w,
                    float4*       __restrict__ out,
                    int n4)
{
    // Per-layer constants, each duplicated into both f32x2 lanes:
    // fwd[i] = {aw, m00, m01, c0, m10, m11, c1}
    // inv[i] = {-aw, u00, u01, d0, u10, u11, d1}
    __shared__ u64 s_f[N_LAYERS][7];
    __shared__ u64 s_r[N_LAYERS][7];

    const int t = threadIdx.x;

    if (t < N_LAYERS) {
        const int i = t;
        float m00 = 1.f, m01 = 0.f, m10 = 0.f, m11 = 1.f;
        float c0 = bias_b[2 * i + 0];
        float c1 = bias_b[2 * i + 1];
        #pragma unroll
        for (int j = 0; j < N_SUB; ++j) {
            float w = lin_w[i * N_SUB + j];
            if ((j & 1) == 0) {          // q += w*p
                m00 = fmaf(w, m10, m00);
                m01 = fmaf(w, m11, m01);
                c0  = fmaf(w, c1,  c0);
            } else {                      // p += w*q
                m10 = fmaf(w, m00, m10);
                m11 = fmaf(w, m01, m11);
                c1  = fmaf(w, c0,  c1);
            }
        }
        float aw = act_w[i];
        s_f[i][0] = pack2(aw,  aw);
        s_f[i][1] = pack2(m00, m00);
        s_f[i][2] = pack2(m01, m01);
        s_f[i][3] = pack2(c0,  c0);
        s_f[i][4] = pack2(m10, m10);
        s_f[i][5] = pack2(m11, m11);
        s_f[i][6] = pack2(c1,  c1);
    } else if (t < 2 * N_LAYERS) {
        const int i = t - N_LAYERS;
        float u00 = 1.f, u01 = 0.f, u10 = 0.f, u11 = 1.f;
        float d0 = 0.f, d1 = 0.f;
        #pragma unroll
        for (int j = N_SUB - 1; j >= 0; --j) {
            float w = lin_w[i * N_SUB + j];
            if ((j & 1) == 0) {          // q -= w*p
                u00 = fmaf(-w, u10, u00);
                u01 = fmaf(-w, u11, u01);
                d0  = fmaf(-w, d1,  d0);
            } else {                      // p -= w*q
                u10 = fmaf(-w, u00, u10);
                u11 = fmaf(-w, u01, u11);
                d1  = fmaf(-w, d0,  d1);
            }
        }
        d0 -= bias_b[2 * i + 0];
        d1 -= bias_b[2 * i + 1];
        float naw = -act_w[i];
        s_r[i][0] = pack2(naw, naw);
        s_r[i][1] = pack2(u00, u00);
        s_r[i][2] = pack2(u01, u01);
        s_r[i][3] = pack2(d0,  d0);
        s_r[i][4] = pack2(u10, u10);
        s_r[i][5] = pack2(u11, u11);
        s_r[i][6] = pack2(d1,  d1);
    }
    __syncthreads();

    const int base = blockIdx.x * (TPB * PAIRS) + t;

    u64 q2[PAIRS], p2[PAIRS];
    #pragma unroll
    for (int e = 0; e < PAIRS; ++e) {
        int idx = base + e * TPB;
        if (idx < n4) {
            float4 v = x[idx];            // {q0, p0, q1, p1}
            q2[e] = pack2(v.x, v.z);
            p2[e] = pack2(v.y, v.w);
        } else {
            q2[e] = 0ULL; p2[e] = 0ULL;
        }
    }

    // ---------------- forward chain ----------------
    #pragma unroll 2
    for (int i = 0; i < N_LAYERS; i += 2) {
        {   // even layer: q += aw*tanh(p), then affine
            u64 aw  = s_f[i][0];
            u64 m00 = s_f[i][1], m01 = s_f[i][2], c0 = s_f[i][3];
            u64 m10 = s_f[i][4], m11 = s_f[i][5], c1 = s_f[i][6];
            #pragma unroll
            for (int e = 0; e < PAIRS; ++e) {
                q2[e] = fma2(aw, tanh2(p2[e]), q2[e]);
                u64 nq = fma2(m00, q2[e], fma2(m01, p2[e], c0));
                u64 np = fma2(m10, q2[e], fma2(m11, p2[e], c1));
                q2[e] = nq; p2[e] = np;
            }
        }
        {   // odd layer: p += aw*tanh(q), then affine
            u64 aw  = s_f[i + 1][0];
            u64 m00 = s_f[i + 1][1], m01 = s_f[i + 1][2], c0 = s_f[i + 1][3];
            u64 m10 = s_f[i + 1][4], m11 = s_f[i + 1][5], c1 = s_f[i + 1][6];
            #pragma unroll
            for (int e = 0; e < PAIRS; ++e) {
                p2[e] = fma2(aw, tanh2(q2[e]), p2[e]);
                u64 nq = fma2(m00, q2[e], fma2(m01, p2[e], c0));
                u64 np = fma2(m10, q2[e], fma2(m11, p2[e], c1));
                q2[e] = nq; p2[e] = np;
            }
        }
    }

    // time reversal: p = -p
    #pragma unroll
    for (int e = 0; e < PAIRS; ++e) p2[e] ^= SIGNMASK2;

    // ---------------- inverse chain ----------------
    #pragma unroll 2
    for (int i = N_LAYERS - 2; i >= 0; i -= 2) {
        {   // odd layer i+1: inverse affine, then p -= aw*tanh(q)
            u64 naw = s_r[i + 1][0];
            u64 u00 = s_r[i + 1][1], u01 = s_r[i + 1][2], d0 = s_r[i + 1][3];
            u64 u10 = s_r[i + 1][4], u11 = s_r[i + 1][5], d1 = s_r[i + 1][6];
            #pragma unroll
            for (int e = 0; e < PAIRS; ++e) {
                u64 nq = fma2(u00, q2[e], fma2(u01, p2[e], d0));
                u64 np = fma2(u10, q2[e], fma2(u11, p2[e], d1));
                q2[e] = nq;
                p2[e] = fma2(naw, tanh2(nq), np);
            }
        }
        {   // even layer i: inverse affine, then q -= aw*tanh(p)
            u64 naw = s_r[i][0];
            u64 u00 = s_r[i][1], u01 = s_r[i][2], d0 = s_r[i][3];
            u64 u10 = s_r[i][4], u11 = s_r[i][5], d1 = s_r[i][6];
            #pragma unroll
            for (int e = 0; e < PAIRS; ++e) {
                u64 nq = fma2(u00, q2[e], fma2(u01, p2[e], d0));
                u64 np = fma2(u10, q2[e], fma2(u11, p2[e], d1));
                p2[e] = np;
                q2[e] = fma2(naw, tanh2(np), nq);
            }
        }
    }

    // output: (q, -p)
    #pragma unroll
    for (int e = 0; e < PAIRS; ++e) {
        int idx = base + e * TPB;
        if (idx < n4) {
            u64 pneg = p2[e] ^ SIGNMASK2;
            float q0, q1, pn0, pn1;
            unpack2(q2[e], q0, q1);
            unpack2(pneg, pn0, pn1);
            out[idx] = make_float4(q0, pn0, q1, pn1);
        }
    }
}

extern "C" void kernel_launch(void* const* d_in, const int* in_sizes, int n_in,
                              void* d_out, int out_size)
{
    const float4* x     = (const float4*)d_in[0];
    const float*  act_w = (const float*)d_in[1];
    const float*  bias_b= (const float*)d_in[2];
    const float*  lin_w = (const float*)d_in[3];
    float4* out = (float4*)d_out;

    int n4 = in_sizes[0] / 4;          // float4 count (= element pairs)

    int per_block = TPB * PAIRS;
    int blocks = (n4 + per_block - 1) / per_block;
    sympnet_kernel<<<blocks, TPB>>>(x, act_w, bias_b, lin_w, out, n4);
}